// round 13
// baseline (speedup 1.0000x reference)
#include <cuda_runtime.h>
#include <cstdint>

// ---------------- problem constants ----------------
#define NB 64
#define HP 58
#define PIX (HP * HP)                  // 3364 padded pixels per image
#define ROWS_TOTAL (NB * PIX)          // 215296
#define GUARD 64
#define AROWS (ROWS_TOTAL + 2 * GUARD)
#define NPXB 6272                      // 200704 / 32 pixels per block
#define NCHUNK (NPXB * 8)              // x8 o-groups of 16

// ---------------- device scratch (no allocation allowed) ----------------
__device__ uint4    g_Abit[AROWS];         // bit-packed sign(x), padded NHWC (bit=1 <=> +1)
__device__ uint32_t g_Wbit2[128 * 4 * 12]; // sign(w) k-major: [o][k][t(9)+pad3]
__device__ float    g_alpha[128];          // -2 * scale_o * gamma_o * rsqrt(var+eps)
__device__ float    g_bias[16 * 128];      // (1152 + corr[type]) * sA + sB
__device__ int      g_ctr;                 // persistent work counter

// ---------------- K1: fused prep: activation signs + weight bits/scales ----------------
// blocks [0, 3712): activation rows (hp = b % 58, n = b / 58)
// blocks [3712, 3840): weight out-channel o = b - 3712
__global__ void __launch_bounds__(128)
k_prep(const float* __restrict__ x, const float* __restrict__ w,
       const float* __restrict__ gamma, const float* __restrict__ beta,
       const float* __restrict__ mean, const float* __restrict__ var) {
    int b = blockIdx.x;
    int tid = threadIdx.x;
    int lane = tid & 31;
    int g = tid >> 5;

    if (b < 3712) {
        // ---- activation role ----
        int hp = b % 58;
        int n = b / 58;
        uint32_t* ga = (uint32_t*)g_Abit;
        size_t rowbase = ((size_t)GUARD + (size_t)n * PIX + (size_t)hp * HP) * 4;

        if (hp == 0 || hp == HP - 1) {
            for (int i = tid; i < HP * 4; i += 128) ga[rowbase + i] = 0u;
            return;
        }

        const float4* xp = (const float4*)(x + ((size_t)(n * 128 + g * 32 + lane)) * 3136
                                             + (size_t)(hp - 1) * 56);
        float4 v[14];
#pragma unroll
        for (int q = 0; q < 14; q++) v[q] = xp[q];

        if (lane == 4) ga[rowbase + g] = 0u;                    // wp = 0
        if (lane == 5) ga[rowbase + (size_t)57 * 4 + g] = 0u;   // wp = 57

#pragma unroll
        for (int q = 0; q < 14; q++) {
            unsigned m0 = __ballot_sync(0xFFFFFFFFu, v[q].x > 0.f);
            unsigned m1 = __ballot_sync(0xFFFFFFFFu, v[q].y > 0.f);
            unsigned m2 = __ballot_sync(0xFFFFFFFFu, v[q].z > 0.f);
            unsigned m3 = __ballot_sync(0xFFFFFFFFu, v[q].w > 0.f);
            if (lane < 4) {
                unsigned mj = (lane == 0) ? m0 : (lane == 1) ? m1 : (lane == 2) ? m2 : m3;
                ga[rowbase + (size_t)(q * 4 + lane + 1) * 4 + g] = mj;
            }
        }
        return;
    }

    // ---- weight role ----
    int o = b - 3712;
    int c = tid;              // input channel 0..127
    __shared__ float redf[128];
    __shared__ uint32_t s_w[36];   // [t*4 + k]
    __shared__ int s_col[9];

    if (o == 0 && c == 0) g_ctr = 0;

    const float* wp = w + (o * 128 + c) * 9;
    float wv[9];
    float acc = 0.f;
#pragma unroll
    for (int t = 0; t < 9; t++) { wv[t] = wp[t]; acc += fabsf(wv[t]); }
    redf[c] = acc;

#pragma unroll
    for (int t = 0; t < 9; t++) {
        unsigned m = __ballot_sync(0xFFFFFFFFu, wv[t] > 0.f);
        if (lane == 0) s_w[t * 4 + g] = m;
    }
    __syncthreads();
#pragma unroll
    for (int s = 64; s > 0; s >>= 1) {
        if (c < s) redf[c] += redf[c + s];
        __syncthreads();
    }
    if (c < 36) {
        int t = c % 9;
        int k = c / 9;
        g_Wbit2[(o * 4 + k) * 12 + t] = s_w[t * 4 + k];
    }
    if (c < 9) {
        int t = c;
        uint32_t b0 = s_w[t * 4 + 0], b1 = s_w[t * 4 + 1], b2 = s_w[t * 4 + 2], b3 = s_w[t * 4 + 3];
        s_col[t] = 2 * (__popc(b0) + __popc(b1) + __popc(b2) + __popc(b3)) - 128;
    }
    __syncthreads();
    if (c < 16) {
        float scale = redf[0] * (1.0f / 1152.0f);
        float inv = gamma[o] * rsqrtf(var[o] + 1e-5f);
        float sA = scale * inv;
        float sB = beta[o] - mean[o] * inv;
        if (c == 0) g_alpha[o] = -2.0f * sA;
        int type = c;
        int corr = 0;
#pragma unroll
        for (int t = 0; t < 9; t++) {
            int dy = t / 3 - 1, dx = t % 3 - 1;
            bool inval = ((type & 1) && dy < 0) || ((type & 2) && dy > 0) ||
                         ((type & 4) && dx < 0) || ((type & 8) && dx > 0);
            if (inval) corr += s_col[t];
        }
        g_bias[type * 128 + o] = (float)(1152 + corr) * sA + sB;
    }
}

// ---------------- CSA: 3 words -> (sum, carry), 2 LOP3 ----------------
__device__ __forceinline__ void csa(uint32_t a, uint32_t b, uint32_t c,
                                    uint32_t& s, uint32_t& cy) {
    s = a ^ b ^ c;
    cy = (a & b) | (a & c) | (b & c);
}

__device__ __forceinline__ void stcs(float* p, float v) {
    asm volatile("st.global.cs.f32 [%0], %1;" :: "l"(p), "f"(v) : "memory");
}

// ---------------- K2: warp-persistent XNOR-popcount conv + BN + residual ----------------
// k-halves processed sequentially within the thread: only 18 A-words live at once
// -> fits 64 regs -> 8 CTAs/SM (smem 25 KB).
__global__ void __launch_bounds__(128, 8)
k_pop(const float* __restrict__ x, float* __restrict__ out) {
    __shared__ uint32_t sW[128 * 48];   // 24 KB, [o][k][12]
    __shared__ float s_alpha[128];
    __shared__ float s_bias0[128];      // interior (type 0) bias

    int tid = threadIdx.x;
    for (int i = tid; i < 128 * 48; i += 128) sW[i] = g_Wbit2[i];
    if (tid < 128) { s_alpha[tid] = g_alpha[tid]; s_bias0[tid] = g_bias[tid]; }
    __syncthreads();

    const int lane = tid & 31;
    const uint2* ga2 = (const uint2*)g_Abit;

    for (;;) {
        int chunk;
        if (lane == 0) chunk = atomicAdd(&g_ctr, 1);
        chunk = __shfl_sync(0xFFFFFFFFu, chunk, 0);
        if (chunk >= NCHUNK) break;

        int og8 = chunk & 7;            // which group of 16 out-channels
        int pb = chunk >> 3;            // 32-pixel block
        int p = pb * 32 + lane;
        int n = p / 3136;
        int rem = p - n * 3136;
        int h = rem / 56;
        int w = rem - h * 56;

        int arow = GUARD + n * PIX + (h + 1) * HP + (w + 1);
        int type = (h == 0 ? 1 : 0) | (h == 55 ? 2 : 0) | (w == 0 ? 4 : 0) | (w == 55 ? 8 : 0);
        int base = n * 401408 + h * 56 + w;

        int Dp[16];
#pragma unroll
        for (int j = 0; j < 16; j++) Dp[j] = 0;

#pragma unroll
        for (int kh = 0; kh < 2; kh++) {
            // this half's 18 tap words
            uint32_t Aw[18];
#pragma unroll
            for (int t = 0; t < 9; t++) {
                int dy = t / 3 - 1, dx = t % 3 - 1;
                uint2 v = ga2[(size_t)(arow + dy * HP + dx) * 2 + kh];
                Aw[t * 2 + 0] = v.x;
                Aw[t * 2 + 1] = v.y;
            }
#pragma unroll 4
            for (int j = 0; j < 16; j++) {
                int o = og8 * 16 + j;
                int acc1 = 0, acc2 = 0;
#pragma unroll
                for (int kk = 0; kk < 2; kk++) {
                    const uint32_t* wk = sW + o * 48 + (kh * 2 + kk) * 12;
                    uint4 w03 = *(const uint4*)(wk);
                    uint4 w47 = *(const uint4*)(wk + 4);
                    uint32_t w8 = wk[8];
                    uint32_t x0 = Aw[0 * 2 + kk] ^ w03.x;
                    uint32_t x1 = Aw[1 * 2 + kk] ^ w03.y;
                    uint32_t x2 = Aw[2 * 2 + kk] ^ w03.z;
                    uint32_t x3 = Aw[3 * 2 + kk] ^ w03.w;
                    uint32_t x4 = Aw[4 * 2 + kk] ^ w47.x;
                    uint32_t x5 = Aw[5 * 2 + kk] ^ w47.y;
                    uint32_t x6 = Aw[6 * 2 + kk] ^ w47.z;
                    uint32_t x7 = Aw[7 * 2 + kk] ^ w47.w;
                    uint32_t x8 = Aw[8 * 2 + kk] ^ w8;
                    uint32_t s0, c0, s1, c1, s2, c2, s3, c3;
                    csa(x0, x1, x2, s0, c0);
                    csa(x3, x4, x5, s1, c1);
                    csa(x6, x7, x8, s2, c2);
                    csa(s0, s1, s2, s3, c3);
                    acc1 += __popc(s3);
                    acc2 += __popc(c0) + __popc(c1) + __popc(c2) + __popc(c3);
                }
                Dp[j] += acc1 + 2 * acc2;
            }
        }

        // ---- epilogue ----
        const float* xr = x + base;
        float* outp = out + base;
#pragma unroll 4
        for (int j = 0; j < 16; j++) {
            int o = og8 * 16 + j;
            float bias = (type == 0) ? s_bias0[o] : __ldg(&g_bias[type * 128 + o]);
            float xv = xr[o * 3136];
            stcs(outp + o * 3136, fmaf((float)Dp[j], s_alpha[o], bias) + xv);
        }
    }
}

// ---------------- launch ----------------
extern "C" void kernel_launch(void* const* d_in, const int* in_sizes, int n_in,
                              void* d_out, int out_size) {
    (void)in_sizes; (void)n_in; (void)out_size;
    const float* x     = (const float*)d_in[0];
    const float* w     = (const float*)d_in[1];
    const float* gamma = (const float*)d_in[2];
    const float* beta  = (const float*)d_in[3];
    const float* mean  = (const float*)d_in[4];
    const float* var   = (const float*)d_in[5];
    float* out = (float*)d_out;

    k_prep<<<3840, 128>>>(x, w, gamma, beta, mean, var);

    int dev = 0;
    cudaGetDevice(&dev);
    int smc = 0;
    if (cudaDeviceGetAttribute(&smc, cudaDevAttrMultiProcessorCount, dev) != cudaSuccess || smc <= 0)
        smc = 148;
    k_pop<<<smc * 8, 128>>>(x, out);
}

// round 14
// speedup vs baseline: 1.0983x; 1.0983x over previous
#include <cuda_runtime.h>
#include <cstdint>

// ---------------- problem constants ----------------
#define NB 64
#define HP 58
#define PIX (HP * HP)                  // 3364 padded pixels per image
#define ROWS_TOTAL (NB * PIX)          // 215296
#define GUARD 64
#define AROWS (ROWS_TOTAL + 2 * GUARD)
#define NPXB 6272                      // 200704 / 32 pixels per block
#define NCHUNK (NPXB * 8)              // x8 o-groups of 16

// ---------------- device scratch (no allocation allowed) ----------------
__device__ uint4    g_Abit[AROWS];         // bit-packed sign(x), padded NHWC (bit=1 <=> +1)
__device__ uint32_t g_Wbit2[128 * 4 * 12]; // sign(w) k-major: [o][k][t(9)+pad3]
__device__ float    g_alpha[128];          // -2 * scale_o * gamma_o * rsqrt(var+eps)
__device__ float    g_bias[16 * 128];      // (1152 + corr[type]) * sA + sB
__device__ int      g_ctr;                 // persistent work counter

// ---------------- K1: fused prep: activation signs + weight bits/scales ----------------
// blocks [0, 3712): activation rows (hp = b % 58, n = b / 58)
// blocks [3712, 3840): weight out-channel o = b - 3712
__global__ void __launch_bounds__(128)
k_prep(const float* __restrict__ x, const float* __restrict__ w,
       const float* __restrict__ gamma, const float* __restrict__ beta,
       const float* __restrict__ mean, const float* __restrict__ var) {
    int b = blockIdx.x;
    int tid = threadIdx.x;
    int lane = tid & 31;
    int g = tid >> 5;

    if (b < 3712) {
        // ---- activation role ----
        int hp = b % 58;
        int n = b / 58;
        uint32_t* ga = (uint32_t*)g_Abit;
        size_t rowbase = ((size_t)GUARD + (size_t)n * PIX + (size_t)hp * HP) * 4;

        if (hp == 0 || hp == HP - 1) {
            for (int i = tid; i < HP * 4; i += 128) ga[rowbase + i] = 0u;
            return;
        }

        const float4* xp = (const float4*)(x + ((size_t)(n * 128 + g * 32 + lane)) * 3136
                                             + (size_t)(hp - 1) * 56);
        float4 v[14];
#pragma unroll
        for (int q = 0; q < 14; q++) v[q] = xp[q];

        if (lane == 4) ga[rowbase + g] = 0u;                    // wp = 0
        if (lane == 5) ga[rowbase + (size_t)57 * 4 + g] = 0u;   // wp = 57

#pragma unroll
        for (int q = 0; q < 14; q++) {
            unsigned m0 = __ballot_sync(0xFFFFFFFFu, v[q].x > 0.f);
            unsigned m1 = __ballot_sync(0xFFFFFFFFu, v[q].y > 0.f);
            unsigned m2 = __ballot_sync(0xFFFFFFFFu, v[q].z > 0.f);
            unsigned m3 = __ballot_sync(0xFFFFFFFFu, v[q].w > 0.f);
            if (lane < 4) {
                unsigned mj = (lane == 0) ? m0 : (lane == 1) ? m1 : (lane == 2) ? m2 : m3;
                ga[rowbase + (size_t)(q * 4 + lane + 1) * 4 + g] = mj;
            }
        }
        return;
    }

    // ---- weight role ----
    int o = b - 3712;
    int c = tid;              // input channel 0..127
    __shared__ float redf[128];
    __shared__ uint32_t s_w[36];   // [t*4 + k]
    __shared__ int s_col[9];

    if (o == 0 && c == 0) g_ctr = 0;

    const float* wp = w + (o * 128 + c) * 9;
    float wv[9];
    float acc = 0.f;
#pragma unroll
    for (int t = 0; t < 9; t++) { wv[t] = wp[t]; acc += fabsf(wv[t]); }
    redf[c] = acc;

#pragma unroll
    for (int t = 0; t < 9; t++) {
        unsigned m = __ballot_sync(0xFFFFFFFFu, wv[t] > 0.f);
        if (lane == 0) s_w[t * 4 + g] = m;
    }
    __syncthreads();
#pragma unroll
    for (int s = 64; s > 0; s >>= 1) {
        if (c < s) redf[c] += redf[c + s];
        __syncthreads();
    }
    if (c < 36) {
        int t = c % 9;
        int k = c / 9;
        g_Wbit2[(o * 4 + k) * 12 + t] = s_w[t * 4 + k];
    }
    if (c < 9) {
        int t = c;
        uint32_t b0 = s_w[t * 4 + 0], b1 = s_w[t * 4 + 1], b2 = s_w[t * 4 + 2], b3 = s_w[t * 4 + 3];
        s_col[t] = 2 * (__popc(b0) + __popc(b1) + __popc(b2) + __popc(b3)) - 128;
    }
    __syncthreads();
    if (c < 16) {
        float scale = redf[0] * (1.0f / 1152.0f);
        float inv = gamma[o] * rsqrtf(var[o] + 1e-5f);
        float sA = scale * inv;
        float sB = beta[o] - mean[o] * inv;
        if (c == 0) g_alpha[o] = -2.0f * sA;
        int type = c;
        int corr = 0;
#pragma unroll
        for (int t = 0; t < 9; t++) {
            int dy = t / 3 - 1, dx = t % 3 - 1;
            bool inval = ((type & 1) && dy < 0) || ((type & 2) && dy > 0) ||
                         ((type & 4) && dx < 0) || ((type & 8) && dx > 0);
            if (inval) corr += s_col[t];
        }
        g_bias[type * 128 + o] = (float)(1152 + corr) * sA + sB;
    }
}

// ---------------- CSA: 3 words -> (sum, carry), 2 LOP3 ----------------
__device__ __forceinline__ void csa(uint32_t a, uint32_t b, uint32_t c,
                                    uint32_t& s, uint32_t& cy) {
    s = a ^ b ^ c;
    cy = (a & b) | (a & c) | (b & c);
}

__device__ __forceinline__ void stcs(float* p, float v) {
    asm volatile("st.global.cs.f32 [%0], %1;" :: "l"(p), "f"(v) : "memory");
}

// ---------------- K2: warp-persistent XNOR-popcount conv + BN + residual ----------------
// R10-measured-best configuration: Aw[36] resident, 16-o chunks, plain CSA tree,
// full bias table in smem, 6 CTAs/SM.
__global__ void __launch_bounds__(128, 6)
k_pop(const float* __restrict__ x, float* __restrict__ out) {
    __shared__ uint32_t sW[128 * 48];   // 24 KB, [o][k][12]
    __shared__ float s_bias[16 * 128];  // 8 KB
    __shared__ float s_alpha[128];

    int tid = threadIdx.x;
    for (int i = tid; i < 128 * 48; i += 128) sW[i] = g_Wbit2[i];
    for (int i = tid; i < 16 * 128; i += 128) s_bias[i] = g_bias[i];
    if (tid < 128) s_alpha[tid] = g_alpha[tid];
    __syncthreads();

    const int lane = tid & 31;

    for (;;) {
        int chunk;
        if (lane == 0) chunk = atomicAdd(&g_ctr, 1);
        chunk = __shfl_sync(0xFFFFFFFFu, chunk, 0);
        if (chunk >= NCHUNK) break;

        int og8 = chunk & 7;            // which group of 16 out-channels
        int pb = chunk >> 3;            // 32-pixel block
        int p = pb * 32 + lane;
        int n = p / 3136;
        int rem = p - n * 3136;
        int h = rem / 56;
        int w = rem - h * 56;

        // 9 tap words -> 36 u32 in registers (component-major access: Aw[t*4+k])
        int arow = GUARD + n * PIX + (h + 1) * HP + (w + 1);
        uint32_t Aw[36];
#pragma unroll
        for (int t = 0; t < 9; t++) {
            int dy = t / 3 - 1, dx = t % 3 - 1;
            uint4 v = g_Abit[arow + dy * HP + dx];
            Aw[t * 4 + 0] = v.x; Aw[t * 4 + 1] = v.y;
            Aw[t * 4 + 2] = v.z; Aw[t * 4 + 3] = v.w;
        }
        int type = (h == 0 ? 1 : 0) | (h == 55 ? 2 : 0) | (w == 0 ? 4 : 0) | (w == 55 ? 8 : 0);
        const float* s_biasT = s_bias + type * 128;
        int base = n * 401408 + h * 56 + w;
        const float* xr = x + base;
        float* outp = out + base;

#pragma unroll 1
        for (int oq = 0; oq < 4; oq++) {
#pragma unroll
            for (int j = 0; j < 4; j++) {
                int o = og8 * 16 + oq * 4 + j;
                int acc1 = 0, acc2 = 0;
#pragma unroll
                for (int k = 0; k < 4; k++) {
                    const uint32_t* wk = sW + o * 48 + k * 12;
                    uint4 w03 = *(const uint4*)(wk);
                    uint4 w47 = *(const uint4*)(wk + 4);
                    uint32_t w8 = wk[8];
                    uint32_t x0 = Aw[0 * 4 + k] ^ w03.x;
                    uint32_t x1 = Aw[1 * 4 + k] ^ w03.y;
                    uint32_t x2 = Aw[2 * 4 + k] ^ w03.z;
                    uint32_t x3 = Aw[3 * 4 + k] ^ w03.w;
                    uint32_t x4 = Aw[4 * 4 + k] ^ w47.x;
                    uint32_t x5 = Aw[5 * 4 + k] ^ w47.y;
                    uint32_t x6 = Aw[6 * 4 + k] ^ w47.z;
                    uint32_t x7 = Aw[7 * 4 + k] ^ w47.w;
                    uint32_t x8 = Aw[8 * 4 + k] ^ w8;
                    uint32_t s0, c0, s1, c1, s2, c2, s3, c3;
                    csa(x0, x1, x2, s0, c0);
                    csa(x3, x4, x5, s1, c1);
                    csa(x6, x7, x8, s2, c2);
                    csa(s0, s1, s2, s3, c3);
                    acc1 += __popc(s3);
                    acc2 += __popc(c0) + __popc(c1) + __popc(c2) + __popc(c3);
                }
                int D = acc1 + 2 * acc2;
                float xv = xr[o * 3136];
                stcs(outp + o * 3136, fmaf((float)D, s_alpha[o], s_biasT[o]) + xv);
            }
        }
    }
}

// ---------------- launch ----------------
extern "C" void kernel_launch(void* const* d_in, const int* in_sizes, int n_in,
                              void* d_out, int out_size) {
    (void)in_sizes; (void)n_in; (void)out_size;
    const float* x     = (const float*)d_in[0];
    const float* w     = (const float*)d_in[1];
    const float* gamma = (const float*)d_in[2];
    const float* beta  = (const float*)d_in[3];
    const float* mean  = (const float*)d_in[4];
    const float* var   = (const float*)d_in[5];
    float* out = (float*)d_out;

    k_prep<<<3840, 128>>>(x, w, gamma, beta, mean, var);

    int dev = 0;
    cudaGetDevice(&dev);
    int smc = 0;
    if (cudaDeviceGetAttribute(&smc, cudaDevAttrMultiProcessorCount, dev) != cudaSuccess || smc <= 0)
        smc = 148;
    k_pop<<<smc * 6, 128>>>(x, out);
}